// round 1
// baseline (speedup 1.0000x reference)
#include <cuda_runtime.h>
#include <math.h>

#define M_TOK 32768
#define DMODEL 1024
#define CD 256
#define NC 4096

__device__ float g_half_norm[NC];

// ---------------------------------------------------------------------------
// GEMM1: z_raw = x @ W_down + b_down   (M=32768, K=1024, N=256)
// Tile: BM=128, BN=128, BK=16, 256 threads, 8x8 micro-tile per thread.
// ---------------------------------------------------------------------------
__global__ __launch_bounds__(256, 1)
void gemm1_kernel(const float* __restrict__ x, const float* __restrict__ W,
                  const float* __restrict__ b, float* __restrict__ z) {
    __shared__ float As[128 * 17];   // [m][k], padded
    __shared__ float Bs[16 * 128];   // [k][n]

    const int t  = threadIdx.x;
    const int tx = t & 15;
    const int ty = t >> 4;
    const int rowBase = blockIdx.x * 128;
    const int colBase = blockIdx.y * 128;

    float acc[8][8];
#pragma unroll
    for (int i = 0; i < 8; i++)
#pragma unroll
        for (int j = 0; j < 8; j++) acc[i][j] = 0.0f;

    for (int kt = 0; kt < DMODEL; kt += 16) {
        // Load A tile: 128 rows x 16 k  (2 float4 per thread)
#pragma unroll
        for (int p = 0; p < 2; p++) {
            int r = (t >> 2) + 64 * p;
            int c = (t & 3) * 4;
            float4 v = *(const float4*)&x[(size_t)(rowBase + r) * DMODEL + kt + c];
            As[r * 17 + c + 0] = v.x;
            As[r * 17 + c + 1] = v.y;
            As[r * 17 + c + 2] = v.z;
            As[r * 17 + c + 3] = v.w;
        }
        // Load B tile: 16 k x 128 n  (2 float4 per thread)
#pragma unroll
        for (int p = 0; p < 2; p++) {
            int kr = (t >> 5) + 8 * p;
            int c  = (t & 31) * 4;
            float4 v = *(const float4*)&W[(size_t)(kt + kr) * CD + colBase + c];
            *(float4*)&Bs[kr * 128 + c] = v;
        }
        __syncthreads();

#pragma unroll
        for (int k = 0; k < 16; k++) {
            float af[8], bf[8];
#pragma unroll
            for (int i = 0; i < 8; i++) af[i] = As[(ty + 16 * i) * 17 + k];
#pragma unroll
            for (int j = 0; j < 8; j++) bf[j] = Bs[k * 128 + tx + 16 * j];
#pragma unroll
            for (int i = 0; i < 8; i++)
#pragma unroll
                for (int j = 0; j < 8; j++)
                    acc[i][j] = fmaf(af[i], bf[j], acc[i][j]);
        }
        __syncthreads();
    }

    float bias[8];
#pragma unroll
    for (int j = 0; j < 8; j++) bias[j] = b[colBase + tx + 16 * j];

#pragma unroll
    for (int i = 0; i < 8; i++) {
        int row = rowBase + ty + 16 * i;
#pragma unroll
        for (int j = 0; j < 8; j++) {
            z[(size_t)row * CD + colBase + tx + 16 * j] = acc[i][j] + bias[j];
        }
    }
}

// ---------------------------------------------------------------------------
// Normalize rows of z in place: z = z / (||z|| + 1e-6). One warp per row.
// ---------------------------------------------------------------------------
__global__ __launch_bounds__(256)
void normalize_kernel(float* __restrict__ z) {
    const int warp = threadIdx.x >> 5;
    const int lane = threadIdx.x & 31;
    const int row  = blockIdx.x * 8 + warp;

    float4* z4 = (float4*)z;
    size_t base = (size_t)row * 64;  // 256 floats = 64 float4
    float4 v0 = z4[base + lane];
    float4 v1 = z4[base + 32 + lane];

    float s = v0.x * v0.x + v0.y * v0.y + v0.z * v0.z + v0.w * v0.w
            + v1.x * v1.x + v1.y * v1.y + v1.z * v1.z + v1.w * v1.w;
#pragma unroll
    for (int o = 16; o > 0; o >>= 1) s += __shfl_xor_sync(0xFFFFFFFFu, s, o);

    float inv = 1.0f / (sqrtf(s) + 1e-6f);
    v0.x *= inv; v0.y *= inv; v0.z *= inv; v0.w *= inv;
    v1.x *= inv; v1.y *= inv; v1.z *= inv; v1.w *= inv;
    z4[base + lane]      = v0;
    z4[base + 32 + lane] = v1;
}

// ---------------------------------------------------------------------------
// Half code norms: g_half_norm[c] = 0.5 * sum(cb[c][:]^2). One warp per code.
// ---------------------------------------------------------------------------
__global__ __launch_bounds__(256)
void halfnorm_kernel(const float* __restrict__ cb) {
    const int warp = threadIdx.x >> 5;
    const int lane = threadIdx.x & 31;
    const int code = blockIdx.x * 8 + warp;

    const float4* c4 = (const float4*)cb;
    size_t base = (size_t)code * 64;
    float4 v0 = c4[base + lane];
    float4 v1 = c4[base + 32 + lane];
    float s = v0.x * v0.x + v0.y * v0.y + v0.z * v0.z + v0.w * v0.w
            + v1.x * v1.x + v1.y * v1.y + v1.z * v1.z + v1.w * v1.w;
#pragma unroll
    for (int o = 16; o > 0; o >>= 1) s += __shfl_xor_sync(0xFFFFFFFFu, s, o);
    if (lane == 0) g_half_norm[code] = 0.5f * s;
}

// ---------------------------------------------------------------------------
// Fused score GEMM + argmax + index write + hard_codes gather.
// Block: 128 tokens, loops over all 4095 codes in 32 tiles of 128.
// score(row, code) = z.c - 0.5*||c||^2 ; maximize == minimize squared dist.
// z tile (128x256, 128KB) staged in smem once; codebook streamed from L2.
// ---------------------------------------------------------------------------
#define K2_SMEM_FLOATS (128 * 256 + 128 * 33)

__global__ __launch_bounds__(256, 1)
void quant_kernel(const float* __restrict__ z, const float* __restrict__ cb,
                  float* __restrict__ out_idx, float* __restrict__ out_hard) {
    extern __shared__ float smem[];
    float* z_s  = smem;               // [128][256]
    float* cb_s = smem + 128 * 256;   // [128][33]  (reused for reduction)
    float* red_val = cb_s;                       // [128][16]
    int*   red_idx = (int*)(cb_s + 128 * 16);    // [128][16]
    int*   row_idx = (int*)(cb_s + 128 * 32);    // [128]

    const int t  = threadIdx.x;
    const int tx = t & 15;
    const int ty = t >> 4;
    const int rowBase = blockIdx.x * 128;

    // Stage z tile (coalesced float4 copy)
    {
        const float4* zg = (const float4*)(z + (size_t)rowBase * CD);
        float4* zs4 = (float4*)z_s;
        for (int i = t; i < 128 * 64; i += 256) zs4[i] = zg[i];
    }
    __syncthreads();

    float best[8];
    int   bidx[8];
#pragma unroll
    for (int i = 0; i < 8; i++) { best[i] = -3.0e38f; bidx[i] = 1; }

    float acc[8][8];
#pragma unroll
    for (int i = 0; i < 8; i++)
#pragma unroll
        for (int j = 0; j < 8; j++) acc[i][j] = 0.0f;

    for (int ct = 0; ct < 32; ct++) {
        const int codeBase = 1 + ct * 128;

        for (int kt = 0; kt < CD; kt += 32) {
            // Load codebook tile: 128 codes x 32 k (4 float4 loads, scalar stores)
#pragma unroll
            for (int p = 0; p < 4; p++) {
                int r = (t >> 3) + 32 * p;
                int c = (t & 7) * 4;
                int code = codeBase + r;
                float4 v;
                if (code < NC)
                    v = *(const float4*)&cb[(size_t)code * CD + kt + c];
                else
                    v = make_float4(0.f, 0.f, 0.f, 0.f);
                cb_s[r * 33 + c + 0] = v.x;
                cb_s[r * 33 + c + 1] = v.y;
                cb_s[r * 33 + c + 2] = v.z;
                cb_s[r * 33 + c + 3] = v.w;
            }
            __syncthreads();

#pragma unroll
            for (int k = 0; k < 32; k++) {
                float zf[8], cf[8];
#pragma unroll
                for (int i = 0; i < 8; i++) zf[i] = z_s[(ty + 16 * i) * 256 + kt + k];
#pragma unroll
                for (int j = 0; j < 8; j++) cf[j] = cb_s[(tx + 16 * j) * 33 + k];
#pragma unroll
                for (int i = 0; i < 8; i++)
#pragma unroll
                    for (int j = 0; j < 8; j++)
                        acc[i][j] = fmaf(zf[i], cf[j], acc[i][j]);
            }
            __syncthreads();
        }

        // Fold into running argmax; reset accumulators
#pragma unroll
        for (int j = 0; j < 8; j++) {
            int code = codeBase + tx + 16 * j;
            if (code <= NC - 1) {
                float hn = g_half_norm[code];
#pragma unroll
                for (int i = 0; i < 8; i++) {
                    float s = acc[i][j] - hn;
                    if (s > best[i]) { best[i] = s; bidx[i] = code; }
                }
            }
#pragma unroll
            for (int i = 0; i < 8; i++) acc[i][j] = 0.0f;
        }
    }

    // Cross-thread reduction over the 16 tx lanes sharing each row
#pragma unroll
    for (int i = 0; i < 8; i++) {
        int r = ty + 16 * i;
        red_val[r * 16 + tx] = best[i];
        red_idx[r * 16 + tx] = bidx[i];
    }
    __syncthreads();

    if (t < 128) {
        float bv = red_val[t * 16];
        int   bi = red_idx[t * 16];
#pragma unroll
        for (int q = 1; q < 16; q++) {
            float v  = red_val[t * 16 + q];
            int   ix = red_idx[t * 16 + q];
            if (v > bv || (v == bv && ix < bi)) { bv = v; bi = ix; }
        }
        row_idx[t] = bi;
        out_idx[rowBase + t] = (float)bi;
    }
    __syncthreads();

    // Gather hard_codes: thread t handles column t for all 128 rows
    for (int r = 0; r < 128; r++) {
        int code = row_idx[r];
        out_hard[(size_t)(rowBase + r) * CD + t] = cb[(size_t)code * CD + t];
    }
}

// ---------------------------------------------------------------------------
// Launch
// ---------------------------------------------------------------------------
extern "C" void kernel_launch(void* const* d_in, const int* in_sizes, int n_in,
                              void* d_out, int out_size) {
    const float* x  = (const float*)d_in[0];   // [32768, 1024]
    const float* cb = (const float*)d_in[1];   // [4096, 256]
    const float* W  = (const float*)d_in[2];   // [1024, 256]
    const float* b  = (const float*)d_in[3];   // [256]

    float* out   = (float*)d_out;
    float* z     = out;                              // [32768, 256]
    float* oidx  = out + (size_t)M_TOK * CD;         // [32768] (indices as float)
    float* ohard = oidx + M_TOK;                     // [32768, 256]

    cudaFuncSetAttribute(quant_kernel, cudaFuncAttributeMaxDynamicSharedMemorySize,
                         K2_SMEM_FLOATS * 4);

    gemm1_kernel<<<dim3(M_TOK / 128, CD / 128), 256>>>(x, W, b, z);
    normalize_kernel<<<M_TOK / 8, 256>>>(z);
    halfnorm_kernel<<<NC / 8, 256>>>(cb);
    quant_kernel<<<M_TOK / 128, 256, K2_SMEM_FLOATS * 4>>>(z, cb, oidx, ohard);
}

// round 3
// speedup vs baseline: 2.8894x; 2.8894x over previous
#include <cuda_runtime.h>
#include <cuda_bf16.h>
#include <math.h>
#include <stdint.h>

#define M_TOK 32768
#define DMODEL 1024
#define CD 256
#define NC 4096

// ---------------------------------------------------------------------------
// Static device scratch
// ---------------------------------------------------------------------------
__device__ float g_half_norm[NC];
__device__ unsigned short g_x_hi[(size_t)M_TOK * DMODEL];
__device__ unsigned short g_x_lo[(size_t)M_TOK * DMODEL];
__device__ unsigned short g_w_hi[(size_t)CD * DMODEL];   // transposed [n][k]
__device__ unsigned short g_w_lo[(size_t)CD * DMODEL];
__device__ unsigned short g_z_hi[(size_t)M_TOK * CD];
__device__ unsigned short g_z_lo[(size_t)M_TOK * CD];
__device__ unsigned short g_cb_hi[(size_t)NC * CD];
__device__ unsigned short g_cb_lo[(size_t)NC * CD];

// ---------------------------------------------------------------------------
// PTX helpers (all baseline sm_80-era features: valid on plain sm_103)
// ---------------------------------------------------------------------------
__device__ __forceinline__ uint32_t smem_u32(const void* p) {
    uint32_t a;
    asm("{ .reg .u64 t; cvta.to.shared.u64 t, %1; cvt.u32.u64 %0, t; }" : "=r"(a) : "l"(p));
    return a;
}
__device__ __forceinline__ void cp16(uint32_t dst, const void* src) {
    asm volatile("cp.async.cg.shared.global [%0], [%1], 16;" :: "r"(dst), "l"(src));
}
#define CP_COMMIT() asm volatile("cp.async.commit_group;" ::: "memory")
#define CP_WAIT(n)  asm volatile("cp.async.wait_group %0;" :: "n"(n) : "memory")

#define LDSM4(r0, r1, r2, r3, addr) \
    asm volatile("ldmatrix.sync.aligned.m8n8.x4.shared.b16 {%0,%1,%2,%3}, [%4];" \
                 : "=r"(r0), "=r"(r1), "=r"(r2), "=r"(r3) : "r"(addr))
#define LDSM2(r0, r1, addr) \
    asm volatile("ldmatrix.sync.aligned.m8n8.x2.shared.b16 {%0,%1}, [%2];" \
                 : "=r"(r0), "=r"(r1) : "r"(addr))

#define MMA16816(c, a, b) \
    asm volatile("mma.sync.aligned.m16n8k16.row.col.f32.bf16.bf16.f32 " \
                 "{%0,%1,%2,%3}, {%4,%5,%6,%7}, {%8,%9}, {%0,%1,%2,%3};" \
                 : "+f"((c)[0]), "+f"((c)[1]), "+f"((c)[2]), "+f"((c)[3]) \
                 : "r"((a)[0]), "r"((a)[1]), "r"((a)[2]), "r"((a)[3]), \
                   "r"((b)[0]), "r"((b)[1]))

// ---------------------------------------------------------------------------
// hi/lo bf16 split of a float4 -> two packed uint2 (4 bf16 each)
// ---------------------------------------------------------------------------
__device__ __forceinline__ void split4(float4 v, uint2& hi, uint2& lo) {
    float f[4] = {v.x, v.y, v.z, v.w};
    unsigned short h[4], l[4];
#pragma unroll
    for (int i = 0; i < 4; i++) {
        __nv_bfloat16 hb = __float2bfloat16(f[i]);
        h[i] = __bfloat16_as_ushort(hb);
        float r = f[i] - __bfloat162float(hb);
        l[i] = __bfloat16_as_ushort(__float2bfloat16(r));
    }
    hi.x = (uint32_t)h[0] | ((uint32_t)h[1] << 16);
    hi.y = (uint32_t)h[2] | ((uint32_t)h[3] << 16);
    lo.x = (uint32_t)l[0] | ((uint32_t)l[1] << 16);
    lo.y = (uint32_t)l[2] | ((uint32_t)l[3] << 16);
}

// ---------------------------------------------------------------------------
// Prep kernels
// ---------------------------------------------------------------------------
__global__ __launch_bounds__(256)
void conv_x_kernel(const float* __restrict__ x) {
    size_t gid = (size_t)blockIdx.x * 256 + threadIdx.x;   // over M*D/4
    float4 v = *(const float4*)&x[gid * 4];
    uint2 hi, lo; split4(v, hi, lo);
    *(uint2*)&g_x_hi[gid * 4] = hi;
    *(uint2*)&g_x_lo[gid * 4] = lo;
}

__global__ __launch_bounds__(256)
void conv_w_kernel(const float* __restrict__ W) {
    size_t gid = (size_t)blockIdx.x * 256 + threadIdx.x;   // over CD*DMODEL
    int n = (int)(gid >> 10);
    int k = (int)(gid & 1023);
    float v = W[(size_t)k * CD + n];
    __nv_bfloat16 hb = __float2bfloat16(v);
    g_w_hi[gid] = __bfloat16_as_ushort(hb);
    g_w_lo[gid] = __bfloat16_as_ushort(__float2bfloat16(v - __bfloat162float(hb)));
}

__global__ __launch_bounds__(256)
void conv_z_kernel(const float* __restrict__ z) {
    size_t gid = (size_t)blockIdx.x * 256 + threadIdx.x;   // over M*CD/4
    float4 v = *(const float4*)&z[gid * 4];
    uint2 hi, lo; split4(v, hi, lo);
    *(uint2*)&g_z_hi[gid * 4] = hi;
    *(uint2*)&g_z_lo[gid * 4] = lo;
}

__global__ __launch_bounds__(256)
void conv_cb_kernel(const float* __restrict__ cb) {
    size_t gid = (size_t)blockIdx.x * 256 + threadIdx.x;   // over NC*CD/4
    float4 v = *(const float4*)&cb[gid * 4];
    uint2 hi, lo; split4(v, hi, lo);
    *(uint2*)&g_cb_hi[gid * 4] = hi;
    *(uint2*)&g_cb_lo[gid * 4] = lo;
}

__global__ __launch_bounds__(256)
void normalize_kernel(float* __restrict__ z) {
    const int warp = threadIdx.x >> 5;
    const int lane = threadIdx.x & 31;
    const int row  = blockIdx.x * 8 + warp;

    float4* z4 = (float4*)z;
    size_t base = (size_t)row * 64;
    float4 v0 = z4[base + lane];
    float4 v1 = z4[base + 32 + lane];
    float s = v0.x*v0.x + v0.y*v0.y + v0.z*v0.z + v0.w*v0.w
            + v1.x*v1.x + v1.y*v1.y + v1.z*v1.z + v1.w*v1.w;
#pragma unroll
    for (int o = 16; o > 0; o >>= 1) s += __shfl_xor_sync(0xFFFFFFFFu, s, o);
    float inv = 1.0f / (sqrtf(s) + 1e-6f);
    v0.x *= inv; v0.y *= inv; v0.z *= inv; v0.w *= inv;
    v1.x *= inv; v1.y *= inv; v1.z *= inv; v1.w *= inv;
    z4[base + lane]      = v0;
    z4[base + 32 + lane] = v1;
}

__global__ __launch_bounds__(256)
void halfnorm_kernel(const float* __restrict__ cb) {
    const int warp = threadIdx.x >> 5;
    const int lane = threadIdx.x & 31;
    const int code = blockIdx.x * 8 + warp;
    const float4* c4 = (const float4*)cb;
    size_t base = (size_t)code * 64;
    float4 v0 = c4[base + lane];
    float4 v1 = c4[base + 32 + lane];
    float s = v0.x*v0.x + v0.y*v0.y + v0.z*v0.z + v0.w*v0.w
            + v1.x*v1.x + v1.y*v1.y + v1.z*v1.z + v1.w*v1.w;
#pragma unroll
    for (int o = 16; o > 0; o >>= 1) s += __shfl_xor_sync(0xFFFFFFFFu, s, o);
    if (lane == 0) g_half_norm[code] = 0.5f * s;
}

// ---------------------------------------------------------------------------
// GEMM1 (mma.sync): z = x @ W + b, 3-pass bf16 split.
// BM=128, BN=128, BK=64-chunk (4 ksteps of 16). 8 warps: 2(M) x 4(N), 64x32.
// smem: xs[2buf][2hl][128][72], ws[2buf][2hl][128][72]  (stride 72 bf16 = 144B)
// ---------------------------------------------------------------------------
#define G1_SMEM (4 * 18432 + 4 * 18432)   // 147456

__device__ __forceinline__ void g1_load(uint32_t XS, uint32_t WS, int buf, int kc,
                                        int rowBase, int colBase, int t) {
#pragma unroll
    for (int q = 0; q < 8; q++) {
        int i = t + 256 * q;
        int hl = i >> 10, r = (i >> 3) & 127, cc = i & 7;
        const unsigned short* src = (hl ? g_x_lo : g_x_hi)
            + (size_t)(rowBase + r) * DMODEL + kc * 64 + cc * 8;
        cp16(XS + (buf * 2 + hl) * 18432 + r * 144 + cc * 16, src);
    }
#pragma unroll
    for (int q = 0; q < 8; q++) {
        int i = t + 256 * q;
        int hl = i >> 10, r = (i >> 3) & 127, cc = i & 7;
        const unsigned short* src = (hl ? g_w_lo : g_w_hi)
            + (size_t)(colBase + r) * DMODEL + kc * 64 + cc * 8;
        cp16(WS + (buf * 2 + hl) * 18432 + r * 144 + cc * 16, src);
    }
}

__global__ __launch_bounds__(256, 1)
void gemm1_mma_kernel(const float* __restrict__ bias, float* __restrict__ z) {
    extern __shared__ unsigned char smem[];
    const uint32_t sb = smem_u32(smem);
    const uint32_t XS = sb;
    const uint32_t WS = sb + 4 * 18432;

    const int t = threadIdx.x, lane = t & 31, w = t >> 5;
    const int warpM = w & 1, warpN = w >> 1;
    const int rowBase = blockIdx.x * 128;
    const int colBase = blockIdx.y * 128;

    float acc[4][4][4];
#pragma unroll
    for (int mt = 0; mt < 4; mt++)
#pragma unroll
        for (int nt = 0; nt < 4; nt++)
#pragma unroll
            for (int c = 0; c < 4; c++) acc[mt][nt][c] = 0.0f;

    const uint32_t a_row  = warpM * 64 + (lane & 15);
    const uint32_t a_col8 = (lane >> 4) * 8;
    const uint32_t b_row  = warpN * 32 + (lane & 7);
    const uint32_t b_col8 = ((lane >> 3) & 1) * 8;

    g1_load(XS, WS, 0, 0, rowBase, colBase, t);
    CP_COMMIT();

    for (int kc = 0; kc < 16; kc++) {
        const int buf = kc & 1;
        if (kc + 1 < 16) { g1_load(XS, WS, (kc + 1) & 1, kc + 1, rowBase, colBase, t); CP_COMMIT(); CP_WAIT(1); }
        else             { CP_WAIT(0); }
        __syncthreads();

#pragma unroll
        for (int ks = 0; ks < 4; ks++) {
            uint32_t bh[4][2], bl[4][2];
#pragma unroll
            for (int nt = 0; nt < 4; nt++) {
                uint32_t baddr = WS + (buf * 2) * 18432 + ((b_row + nt * 8) * 72 + ks * 16 + b_col8) * 2;
                LDSM2(bh[nt][0], bh[nt][1], baddr);
                LDSM2(bl[nt][0], bl[nt][1], baddr + 18432);
            }
#pragma unroll
            for (int mt = 0; mt < 4; mt++) {
                uint32_t ah[4], al[4];
                uint32_t aaddr = XS + (buf * 2) * 18432 + ((a_row + mt * 16) * 72 + ks * 16 + a_col8) * 2;
                LDSM4(ah[0], ah[1], ah[2], ah[3], aaddr);
                LDSM4(al[0], al[1], al[2], al[3], aaddr + 18432);
#pragma unroll
                for (int nt = 0; nt < 4; nt++) {
                    MMA16816(acc[mt][nt], ah, bh[nt]);
                    MMA16816(acc[mt][nt], ah, bl[nt]);
                    MMA16816(acc[mt][nt], al, bh[nt]);
                }
            }
        }
        __syncthreads();
    }

    // epilogue: + bias, store fp32
    const int row0 = rowBase + warpM * 64 + (lane >> 2);
    const int col0 = colBase + warpN * 32 + (lane & 3) * 2;
#pragma unroll
    for (int mt = 0; mt < 4; mt++) {
#pragma unroll
        for (int nt = 0; nt < 4; nt++) {
            int r0 = row0 + mt * 16;
            int c  = col0 + nt * 8;
            float b0 = __ldg(&bias[c]), b1 = __ldg(&bias[c + 1]);
            *(float2*)&z[(size_t)r0 * CD + c]       = make_float2(acc[mt][nt][0] + b0, acc[mt][nt][1] + b1);
            *(float2*)&z[(size_t)(r0 + 8) * CD + c] = make_float2(acc[mt][nt][2] + b0, acc[mt][nt][3] + b1);
        }
    }
}

// ---------------------------------------------------------------------------
// Quant kernel (mma.sync): scores = z @ cb^T (3-pass) + fused argmax + gather.
// z (hi+lo, full K=256) resident in smem; cb streamed in 64-col chunks.
// smem: z[2hl][128][264] (135168B) + cb[2buf][2hl][128][72] (73728B)
// ---------------------------------------------------------------------------
#define Q_ZBYTES  (2 * 128 * 264 * 2)            // 135168
#define Q_CBBYTES (4 * 18432)                    // 73728
#define Q_SMEM    (Q_ZBYTES + Q_CBBYTES)         // 208896

__device__ __forceinline__ void q_load_cb(uint32_t CBB, int buf, int tt, int kc, int t) {
#pragma unroll
    for (int q = 0; q < 8; q++) {
        int i = t + 256 * q;
        int hl = i >> 10, r = (i >> 3) & 127, cc = i & 7;
        int code = 1 + tt * 128 + r;
        if (code > NC - 1) code = NC - 1;
        const unsigned short* src = (hl ? g_cb_lo : g_cb_hi)
            + (size_t)code * CD + kc * 64 + cc * 8;
        cp16(CBB + (buf * 2 + hl) * 18432 + r * 144 + cc * 16, src);
    }
}

__global__ __launch_bounds__(256, 1)
void quant_mma_kernel(const float* __restrict__ cb,
                      float* __restrict__ out_idx, float* __restrict__ out_hard) {
    extern __shared__ unsigned char smem[];
    const uint32_t sb  = smem_u32(smem);
    const uint32_t ZB  = sb;
    const uint32_t CBB = sb + Q_ZBYTES;

    const int t = threadIdx.x, lane = t & 31, w = t >> 5;
    const int warpM = w & 1, warpN = w >> 1;
    const int rowBase = blockIdx.x * 128;

    // stage z tile (hi|lo), full K
#pragma unroll
    for (int q = 0; q < 32; q++) {
        int i = t + 256 * q;
        int hl = i >> 12, r = (i >> 5) & 127, cc = i & 31;
        const unsigned short* src = (hl ? g_z_lo : g_z_hi)
            + (size_t)(rowBase + r) * CD + cc * 8;
        cp16(ZB + hl * 67584 + r * 528 + cc * 16, src);
    }
    q_load_cb(CBB, 0, 0, 0, t);
    CP_COMMIT();

    float acc[4][4][4];
#pragma unroll
    for (int mt = 0; mt < 4; mt++)
#pragma unroll
        for (int nt = 0; nt < 4; nt++)
#pragma unroll
            for (int c = 0; c < 4; c++) acc[mt][nt][c] = 0.0f;

    float best[8];
    int   bidx[8];
#pragma unroll
    for (int s = 0; s < 8; s++) { best[s] = -3.0e38f; bidx[s] = 1; }

    const uint32_t a_row  = warpM * 64 + (lane & 15);
    const uint32_t a_col8 = (lane >> 4) * 8;
    const uint32_t b_row  = warpN * 32 + (lane & 7);
    const uint32_t b_col8 = ((lane >> 3) & 1) * 8;

    for (int it = 0; it < 128; it++) {
        const int tt = it >> 2, kc = it & 3, buf = it & 1;
        if (it + 1 < 128) { q_load_cb(CBB, (it + 1) & 1, (it + 1) >> 2, (it + 1) & 3, t); CP_COMMIT(); CP_WAIT(1); }
        else              { CP_WAIT(0); }
        __syncthreads();

#pragma unroll
        for (int ks = 0; ks < 4; ks++) {
            const int k = kc * 64 + ks * 16;
            uint32_t bh[4][2], bl[4][2];
#pragma unroll
            for (int nt = 0; nt < 4; nt++) {
                uint32_t baddr = CBB + (buf * 2) * 18432 + ((b_row + nt * 8) * 72 + ks * 16 + b_col8) * 2;
                LDSM2(bh[nt][0], bh[nt][1], baddr);
                LDSM2(bl[nt][0], bl[nt][1], baddr + 18432);
            }
#pragma unroll
            for (int mt = 0; mt < 4; mt++) {
                uint32_t ah[4], al[4];
                uint32_t aaddr = ZB + ((a_row + mt * 16) * 264 + k + a_col8) * 2;
                LDSM4(ah[0], ah[1], ah[2], ah[3], aaddr);
                LDSM4(al[0], al[1], al[2], al[3], aaddr + 67584);
#pragma unroll
                for (int nt = 0; nt < 4; nt++) {
                    MMA16816(acc[mt][nt], ah, bh[nt]);
                    MMA16816(acc[mt][nt], ah, bl[nt]);
                    MMA16816(acc[mt][nt], al, bh[nt]);
                }
            }
        }
        __syncthreads();

        if (kc == 3) {
            const int codeTile = 1 + tt * 128 + warpN * 32;
#pragma unroll
            for (int nt = 0; nt < 4; nt++) {
                int c0 = codeTile + nt * 8 + (lane & 3) * 2;
                float hn0 = (c0 < NC)     ? __ldg(&g_half_norm[c0])     : 0.0f;
                float hn1 = (c0 + 1 < NC) ? __ldg(&g_half_norm[c0 + 1]) : 0.0f;
#pragma unroll
                for (int mt = 0; mt < 4; mt++) {
                    if (c0 < NC) {
                        float s0 = acc[mt][nt][0] - hn0;
                        if (s0 > best[mt * 2])     { best[mt * 2] = s0;     bidx[mt * 2] = c0; }
                        float s2 = acc[mt][nt][2] - hn0;
                        if (s2 > best[mt * 2 + 1]) { best[mt * 2 + 1] = s2; bidx[mt * 2 + 1] = c0; }
                    }
                    if (c0 + 1 < NC) {
                        float s1 = acc[mt][nt][1] - hn1;
                        if (s1 > best[mt * 2])     { best[mt * 2] = s1;     bidx[mt * 2] = c0 + 1; }
                        float s3 = acc[mt][nt][3] - hn1;
                        if (s3 > best[mt * 2 + 1]) { best[mt * 2 + 1] = s3; bidx[mt * 2 + 1] = c0 + 1; }
                    }
                    acc[mt][nt][0] = 0.0f; acc[mt][nt][1] = 0.0f;
                    acc[mt][nt][2] = 0.0f; acc[mt][nt][3] = 0.0f;
                }
            }
        }
    }

    // reduce across the 4 lanes (lane&3) sharing each row, then across warpN
    float* red_val = (float*)(smem + Q_ZBYTES);
    int*   red_idx = (int*)(smem + Q_ZBYTES + 2048);
    int*   row_idx = (int*)(smem + Q_ZBYTES + 4096);

#pragma unroll
    for (int slot = 0; slot < 8; slot++) {
        float v = best[slot]; int ix = bidx[slot];
#pragma unroll
        for (int off = 1; off <= 2; off <<= 1) {
            float ov = __shfl_xor_sync(0xFFFFFFFFu, v, off);
            int   oi = __shfl_xor_sync(0xFFFFFFFFu, ix, off);
            if (ov > v || (ov == v && oi < ix)) { v = ov; ix = oi; }
        }
        if ((lane & 3) == 0) {
            int mt = slot >> 1, h = slot & 1;
            int row = warpM * 64 + mt * 16 + (lane >> 2) + h * 8;
            red_val[row * 4 + warpN] = v;
            red_idx[row * 4 + warpN] = ix;
        }
    }
    __syncthreads();

    if (t < 128) {
        float bv = red_val[t * 4]; int bi = red_idx[t * 4];
#pragma unroll
        for (int q = 1; q < 4; q++) {
            float v = red_val[t * 4 + q]; int ix = red_idx[t * 4 + q];
            if (v > bv || (v == bv && ix < bi)) { bv = v; bi = ix; }
        }
        row_idx[t] = bi;
        out_idx[rowBase + t] = (float)bi;
    }
    __syncthreads();

    for (int r = 0; r < 128; r++) {
        int code = row_idx[r];
        out_hard[(size_t)(rowBase + r) * CD + t] = __ldg(&cb[(size_t)code * CD + t]);
    }
}

// ---------------------------------------------------------------------------
// Launch
// ---------------------------------------------------------------------------
extern "C" void kernel_launch(void* const* d_in, const int* in_sizes, int n_in,
                              void* d_out, int out_size) {
    const float* x  = (const float*)d_in[0];   // [32768, 1024]
    const float* cb = (const float*)d_in[1];   // [4096, 256]
    const float* W  = (const float*)d_in[2];   // [1024, 256]
    const float* b  = (const float*)d_in[3];   // [256]

    float* out   = (float*)d_out;
    float* z     = out;                              // [32768, 256]
    float* oidx  = out + (size_t)M_TOK * CD;         // [32768]
    float* ohard = oidx + M_TOK;                     // [32768, 256]

    cudaFuncSetAttribute(gemm1_mma_kernel, cudaFuncAttributeMaxDynamicSharedMemorySize, G1_SMEM);
    cudaFuncSetAttribute(quant_mma_kernel, cudaFuncAttributeMaxDynamicSharedMemorySize, Q_SMEM);

    conv_x_kernel<<<(int)((size_t)M_TOK * DMODEL / 4 / 256), 256>>>(x);
    conv_w_kernel<<<(CD * DMODEL) / 256, 256>>>(W);
    halfnorm_kernel<<<NC / 8, 256>>>(cb);
    conv_cb_kernel<<<(NC * CD / 4) / 256, 256>>>(cb);

    gemm1_mma_kernel<<<dim3(M_TOK / 128, CD / 128), 256, G1_SMEM>>>(b, z);
    normalize_kernel<<<M_TOK / 8, 256>>>(z);
    conv_z_kernel<<<(M_TOK * CD / 4) / 256, 256>>>(z);

    quant_mma_kernel<<<M_TOK / 128, 256, Q_SMEM>>>(cb, oidx, ohard);
}